// round 1
// baseline (speedup 1.0000x reference)
#include <cuda_runtime.h>
#include <cstdint>

// Problem constants
#define B_ 4
#define S_ 2048
#define D_ 512
#define H_ 8
#define NT 8192               // B*S tokens
#define DH 4096               // D*H
#define ZN 32                 // B*H attention instances
#define ATT_SCALE 0.04419417382415922f   // 512^-0.5

// ---------------- scratch (device globals; no runtime allocation) -------------
__device__ float g_xn[(size_t)NT * D_];                // 16 MB   normalized x
__device__ float g_q[(size_t)ZN * S_ * D_];            // 128 MB  [b,h,s,d]
__device__ float g_k[(size_t)ZN * S_ * D_];            // 128 MB
__device__ float g_v[(size_t)ZN * S_ * D_];            // 128 MB
__device__ float g_scores[(size_t)ZN * S_ * S_];       // 512 MB  [z,s,s]
__device__ float g_attn[(size_t)NT * DH];              // 128 MB  [token, h*512+d]

// ---------------- LayerNorm: one block per row of 512 -------------------------
__global__ void ln_kernel(const float* __restrict__ x,
                          const float* __restrict__ w,
                          const float* __restrict__ b) {
    int row = blockIdx.x;
    int t = threadIdx.x;                       // 128 threads, one float4 each
    const float4* xr = (const float4*)(x + (size_t)row * D_);
    float4 v = xr[t];
    float s  = v.x + v.y + v.z + v.w;
    float q  = v.x * v.x + v.y * v.y + v.z * v.z + v.w * v.w;
#pragma unroll
    for (int o = 16; o > 0; o >>= 1) {
        s += __shfl_xor_sync(0xffffffffu, s, o);
        q += __shfl_xor_sync(0xffffffffu, q, o);
    }
    __shared__ float ss[4], sq[4];
    int wid = t >> 5;
    if ((t & 31) == 0) { ss[wid] = s; sq[wid] = q; }
    __syncthreads();
    s = ss[0] + ss[1] + ss[2] + ss[3];
    q = sq[0] + sq[1] + sq[2] + sq[3];
    float mu  = s * (1.0f / D_);
    float var = q * (1.0f / D_) - mu * mu;
    float r   = rsqrtf(var + 1e-5f);
    float4 wv = ((const float4*)w)[t];
    float4 bv = ((const float4*)b)[t];
    float4 o;
    o.x = (v.x - mu) * r * wv.x + bv.x;
    o.y = (v.y - mu) * r * wv.y + bv.y;
    o.z = (v.z - mu) * r * wv.z + bv.z;
    o.w = (v.w - mu) * r * wv.w + bv.w;
    ((float4*)(g_xn + (size_t)row * D_))[t] = o;
}

// ---------------- GEMM: 128x128x16 tile, 8x8 per thread, 256 threads ----------
// MODE 0: g_xn[8192,512] @ W[512,4096] + bias -> scatter into g_q/g_k/g_v [b,h,s,d]
// MODE 1: per z: Q[2048,512] @ K^T (K stored [2048,512]) * scale -> g_scores
// MODE 2: per z: P[2048,2048] @ V[2048,512] -> g_attn [token, h*512+d]
// MODE 3: g_attn[8192,4096] @ o_w[4096,512] + o_b -> d_out
constexpr int BM = 128, BN = 128, BK = 16;

template <int MODE>
__global__ __launch_bounds__(256, 2)
void gemm_kernel(const float* __restrict__ Bext,
                 const float* __restrict__ bias,
                 float* __restrict__ Cout,
                 int which) {
    // compile-time dims per mode
    constexpr int K   = (MODE == 0) ? 512 : (MODE == 1) ? 512 : (MODE == 2) ? 2048 : 4096;
    constexpr int lda = (MODE == 0) ? 512 : (MODE == 1) ? 512 : (MODE == 2) ? 2048 : 4096;
    constexpr int ldb = (MODE == 0) ? 4096 : (MODE == 1) ? 512 : 512;
    constexpr bool TRANS_B = (MODE == 1);

    int z = blockIdx.z;
    const float* A;
    const float* Bm;
    if (MODE == 0)      { A = g_xn;                              Bm = Bext; }
    else if (MODE == 1) { A = g_q + (size_t)z * S_ * D_;         Bm = g_k + (size_t)z * S_ * D_; }
    else if (MODE == 2) { A = g_scores + ((size_t)z << 22);      Bm = g_v + (size_t)z * S_ * D_; }
    else                { A = g_attn;                            Bm = Bext; }

    __shared__ float As[BK][BM + 4];
    __shared__ float Bs[BK][BN + 4];

    float acc[8][8];
#pragma unroll
    for (int i = 0; i < 8; i++)
#pragma unroll
        for (int j = 0; j < 8; j++) acc[i][j] = 0.0f;

    int tid = threadIdx.x;
    int m0 = blockIdx.y * BM;
    int n0 = blockIdx.x * BN;
    int tr = (tid >> 4) << 3;      // 0..120 step 8 (M within tile)
    int tc = (tid & 15) << 3;      // 0..120 step 8 (N within tile)

    // load assignments
    int aRow = tid >> 2;           // 0..63 (second half adds 64)
    int aK   = (tid & 3) << 2;     // 0,4,8,12
    int bK   = tid >> 5;           // 0..7 (second half adds 8)   (NN only)
    int bN   = (tid & 31) << 2;    // 0..124 step 4               (NN only)

    for (int k0 = 0; k0 < K; k0 += BK) {
#pragma unroll
        for (int i = 0; i < 2; i++) {
            int row = aRow + i * 64;
            const float4 va = *(const float4*)&A[(size_t)(m0 + row) * lda + k0 + aK];
            As[aK + 0][row] = va.x; As[aK + 1][row] = va.y;
            As[aK + 2][row] = va.z; As[aK + 3][row] = va.w;
        }
        if (TRANS_B) {
#pragma unroll
            for (int i = 0; i < 2; i++) {
                int row = aRow + i * 64;
                const float4 vb = *(const float4*)&Bm[(size_t)(n0 + row) * ldb + k0 + aK];
                Bs[aK + 0][row] = vb.x; Bs[aK + 1][row] = vb.y;
                Bs[aK + 2][row] = vb.z; Bs[aK + 3][row] = vb.w;
            }
        } else {
#pragma unroll
            for (int i = 0; i < 2; i++) {
                int kk = bK + i * 8;
                const float4 vb = *(const float4*)&Bm[(size_t)(k0 + kk) * ldb + n0 + bN];
                *(float4*)&Bs[kk][bN] = vb;   // row stride 132 floats = 528B, 16B-aligned
            }
        }
        __syncthreads();
#pragma unroll
        for (int kk = 0; kk < BK; kk++) {
            float a[8], b[8];
            *(float4*)&a[0] = *(const float4*)&As[kk][tr];
            *(float4*)&a[4] = *(const float4*)&As[kk][tr + 4];
            *(float4*)&b[0] = *(const float4*)&Bs[kk][tc];
            *(float4*)&b[4] = *(const float4*)&Bs[kk][tc + 4];
#pragma unroll
            for (int i = 0; i < 8; i++)
#pragma unroll
                for (int j = 0; j < 8; j++)
                    acc[i][j] = fmaf(a[i], b[j], acc[i][j]);
        }
        __syncthreads();
    }

    // ---- epilogue (two float4 stores per output row slice) ----
    float bvals[8];
    if (MODE == 0 || MODE == 3) {
        *(float4*)&bvals[0] = *(const float4*)&bias[n0 + tc];
        *(float4*)&bvals[4] = *(const float4*)&bias[n0 + tc + 4];
    }
#pragma unroll
    for (int i = 0; i < 8; i++) {
        int m = m0 + tr + i;
        int n = n0 + tc;
        float vv[8];
#pragma unroll
        for (int j = 0; j < 8; j++) vv[j] = acc[i][j];

        if (MODE == 0) {
#pragma unroll
            for (int j = 0; j < 8; j++) vv[j] += bvals[j];
            float* C = (which == 0) ? g_q : (which == 1) ? g_k : g_v;
            int bb = m >> 11, s = m & 2047;
            int h = n >> 9, d = n & 511;
            float* dst = C + ((size_t)((bb << 3) + h) * S_ + s) * D_ + d;
            *(float4*)&dst[0] = *(float4*)&vv[0];
            *(float4*)&dst[4] = *(float4*)&vv[4];
        } else if (MODE == 1) {
#pragma unroll
            for (int j = 0; j < 8; j++) vv[j] *= ATT_SCALE;
            float* dst = g_scores + ((size_t)z << 22) + (size_t)m * S_ + n;
            *(float4*)&dst[0] = *(float4*)&vv[0];
            *(float4*)&dst[4] = *(float4*)&vv[4];
        } else if (MODE == 2) {
            int bb = z >> 3, h = z & 7;
            float* dst = g_attn + ((size_t)(bb * S_ + m)) * DH + (h << 9) + n;
            *(float4*)&dst[0] = *(float4*)&vv[0];
            *(float4*)&dst[4] = *(float4*)&vv[4];
        } else {
#pragma unroll
            for (int j = 0; j < 8; j++) vv[j] += bvals[j];
            float* dst = Cout + (size_t)m * D_ + n;
            *(float4*)&dst[0] = *(float4*)&vv[0];
            *(float4*)&dst[4] = *(float4*)&vv[4];
        }
    }
}

// ---------------- row softmax over 2048, one block per row --------------------
__global__ void softmax_kernel() {
    float4* rp = (float4*)(g_scores + ((size_t)blockIdx.x << 11));
    int t = threadIdx.x;                      // 256 threads, 8 floats each
    float4 v0 = rp[t];
    float4 v1 = rp[t + 256];
    float mx = fmaxf(fmaxf(fmaxf(v0.x, v0.y), fmaxf(v0.z, v0.w)),
                     fmaxf(fmaxf(v1.x, v1.y), fmaxf(v1.z, v1.w)));
#pragma unroll
    for (int o = 16; o > 0; o >>= 1) mx = fmaxf(mx, __shfl_xor_sync(0xffffffffu, mx, o));
    __shared__ float sm[8];
    int w = t >> 5;
    if ((t & 31) == 0) sm[w] = mx;
    __syncthreads();
    mx = sm[0];
#pragma unroll
    for (int i = 1; i < 8; i++) mx = fmaxf(mx, sm[i]);

    v0.x = __expf(v0.x - mx); v0.y = __expf(v0.y - mx);
    v0.z = __expf(v0.z - mx); v0.w = __expf(v0.w - mx);
    v1.x = __expf(v1.x - mx); v1.y = __expf(v1.y - mx);
    v1.z = __expf(v1.z - mx); v1.w = __expf(v1.w - mx);
    float s = v0.x + v0.y + v0.z + v0.w + v1.x + v1.y + v1.z + v1.w;
#pragma unroll
    for (int o = 16; o > 0; o >>= 1) s += __shfl_xor_sync(0xffffffffu, s, o);
    __syncthreads();                           // sm reuse
    if ((t & 31) == 0) sm[w] = s;
    __syncthreads();
    s = sm[0] + sm[1] + sm[2] + sm[3] + sm[4] + sm[5] + sm[6] + sm[7];
    float inv = 1.0f / s;
    v0.x *= inv; v0.y *= inv; v0.z *= inv; v0.w *= inv;
    v1.x *= inv; v1.y *= inv; v1.z *= inv; v1.w *= inv;
    rp[t] = v0;
    rp[t + 256] = v1;
}

// ---------------- launch ------------------------------------------------------
extern "C" void kernel_launch(void* const* d_in, const int* in_sizes, int n_in,
                              void* d_out, int out_size) {
    const float* x    = (const float*)d_in[0];
    const float* ln_w = (const float*)d_in[1];
    const float* ln_b = (const float*)d_in[2];
    const float* q_w  = (const float*)d_in[3];
    const float* q_b  = (const float*)d_in[4];
    const float* k_w  = (const float*)d_in[5];
    const float* k_b  = (const float*)d_in[6];
    const float* v_w  = (const float*)d_in[7];
    const float* v_b  = (const float*)d_in[8];
    const float* o_w  = (const float*)d_in[9];
    const float* o_b  = (const float*)d_in[10];
    float* out = (float*)d_out;

    ln_kernel<<<NT, 128>>>(x, ln_w, ln_b);

    dim3 gQKV(DH / BN, NT / BM, 1);            // (32, 64)
    gemm_kernel<0><<<gQKV, 256>>>(q_w, q_b, nullptr, 0);
    gemm_kernel<0><<<gQKV, 256>>>(k_w, k_b, nullptr, 1);
    gemm_kernel<0><<<gQKV, 256>>>(v_w, v_b, nullptr, 2);

    dim3 gS(S_ / BN, S_ / BM, ZN);             // (16, 16, 32)
    gemm_kernel<1><<<gS, 256>>>(nullptr, nullptr, nullptr, 0);

    softmax_kernel<<<ZN * S_, 256>>>();

    dim3 gPV(D_ / BN, S_ / BM, ZN);            // (4, 16, 32)
    gemm_kernel<2><<<gPV, 256>>>(nullptr, nullptr, nullptr, 0);

    dim3 gO(D_ / BN, NT / BM, 1);              // (4, 64)
    gemm_kernel<3><<<gO, 256>>>(o_w, o_b, out, 0);
}

// round 3
// speedup vs baseline: 2.6690x; 2.6690x over previous
#include <cuda_runtime.h>
#include <cstdint>

// ---------------- problem constants ------------------------------------------
#define B_ 4
#define S_ 2048
#define D_ 512
#define H_ 8
#define NT 8192               // B*S tokens
#define DH 4096               // D*H
#define ZN 32                 // B*H attention instances
#define ATT_SCALE 0.04419417382415922f   // 512^-0.5

// ---------------- scratch (device globals; no runtime allocation) -------------
__device__ float g_xn[(size_t)NT * D_];                // 16 MB
__device__ float g_q[(size_t)ZN * S_ * D_];            // 128 MB [z][s][d]
__device__ float g_k[(size_t)ZN * S_ * D_];            // 128 MB [z][s][d]
__device__ float g_v[(size_t)ZN * S_ * D_];            // 128 MB [z][s][d]
__device__ float g_vt[(size_t)ZN * S_ * D_];           // 128 MB [z][d][s]
__device__ float g_scores[(size_t)ZN * S_ * S_];       // 512 MB [z][s][s]
__device__ float g_attn[(size_t)NT * DH];              // 128 MB [token][h*512+d]
__device__ float g_wtq[(size_t)DH * D_];               // 8 MB  W^T [4096][512]
__device__ float g_wtk[(size_t)DH * D_];
__device__ float g_wtv[(size_t)DH * D_];
__device__ float g_wto[(size_t)D_ * DH];               // 8 MB  o_w^T [512][4096]

// ---------------- helpers -----------------------------------------------------
__device__ __forceinline__ float to_tf32(float x) {
    uint32_t u = __float_as_uint(x), o;
    asm("cvt.rna.tf32.f32 %0, %1;" : "=r"(o) : "r"(u));
    return __uint_as_float(o);
}

__device__ __forceinline__ uint32_t smem_u32(const void* p) {
    uint32_t a;
    asm("{ .reg .u64 t; cvta.to.shared.u64 t, %1; cvt.u32.u64 %0, t; }" : "=r"(a) : "l"(p));
    return a;
}

__device__ __forceinline__ void cp16(uint32_t dst, const void* src) {
    asm volatile("cp.async.cg.shared.global [%0], [%1], 16;" :: "r"(dst), "l"(src));
}
#define CP_COMMIT() asm volatile("cp.async.commit_group;")
#define CP_WAIT1()  asm volatile("cp.async.wait_group 1;")
#define CP_WAIT0()  asm volatile("cp.async.wait_group 0;")

__device__ __forceinline__ void mma_tf32(float* c, const uint32_t* a, const uint32_t* b) {
    asm volatile(
        "mma.sync.aligned.m16n8k8.row.col.f32.tf32.tf32.f32 "
        "{%0,%1,%2,%3}, {%4,%5,%6,%7}, {%8,%9}, {%0,%1,%2,%3};"
        : "+f"(c[0]), "+f"(c[1]), "+f"(c[2]), "+f"(c[3])
        : "r"(a[0]), "r"(a[1]), "r"(a[2]), "r"(a[3]), "r"(b[0]), "r"(b[1]));
}

// ---------------- LayerNorm ---------------------------------------------------
__global__ void ln_kernel(const float* __restrict__ x,
                          const float* __restrict__ w,
                          const float* __restrict__ b) {
    int row = blockIdx.x;
    int t = threadIdx.x;                       // 128 threads
    const float4* xr = (const float4*)(x + (size_t)row * D_);
    float4 v = xr[t];
    float s  = v.x + v.y + v.z + v.w;
    float q  = v.x * v.x + v.y * v.y + v.z * v.z + v.w * v.w;
#pragma unroll
    for (int o = 16; o > 0; o >>= 1) {
        s += __shfl_xor_sync(0xffffffffu, s, o);
        q += __shfl_xor_sync(0xffffffffu, q, o);
    }
    __shared__ float ss[4], sq[4];
    int wid = t >> 5;
    if ((t & 31) == 0) { ss[wid] = s; sq[wid] = q; }
    __syncthreads();
    s = ss[0] + ss[1] + ss[2] + ss[3];
    q = sq[0] + sq[1] + sq[2] + sq[3];
    float mu  = s * (1.0f / D_);
    float var = q * (1.0f / D_) - mu * mu;
    float r   = rsqrtf(var + 1e-5f);
    float4 wv = ((const float4*)w)[t];
    float4 bv = ((const float4*)b)[t];
    float4 o;
    o.x = to_tf32((v.x - mu) * r * wv.x + bv.x);
    o.y = to_tf32((v.y - mu) * r * wv.y + bv.y);
    o.z = to_tf32((v.z - mu) * r * wv.z + bv.z);
    o.w = to_tf32((v.w - mu) * r * wv.w + bv.w);
    ((float4*)(g_xn + (size_t)row * D_))[t] = o;
}

// ---------------- 32x32 tiled transpose (with tf32 rounding for weights) ------
// sel: 0 q_w, 1 k_w, 2 v_w  ([512,4096] -> [4096,512])
//      3 o_w ([4096,512] -> [512,4096])
//      4 g_v slice z ([2048,512] -> g_vt [512,2048])  (already tf32)
__global__ void transpose_kernel(const float* __restrict__ in_ext, int sel, int R, int C) {
    __shared__ float tile[32][33];
    int z = blockIdx.z;
    const float* in;
    float* out;
    if (sel == 0)      { in = in_ext; out = g_wtq; }
    else if (sel == 1) { in = in_ext; out = g_wtk; }
    else if (sel == 2) { in = in_ext; out = g_wtv; }
    else if (sel == 3) { in = in_ext; out = g_wto; }
    else               { in = g_v + (size_t)z * S_ * D_; out = g_vt + (size_t)z * S_ * D_; }

    int x  = blockIdx.x * 32 + threadIdx.x;
    int y0 = blockIdx.y * 32;
#pragma unroll
    for (int j = 0; j < 32; j += 8) {
        float v = in[(size_t)(y0 + threadIdx.y + j) * C + x];
        tile[threadIdx.y + j][threadIdx.x] = (sel < 4) ? to_tf32(v) : v;
    }
    __syncthreads();
    int ox  = y0 + threadIdx.x;
    int oy0 = blockIdx.x * 32;
#pragma unroll
    for (int j = 0; j < 32; j += 8)
        out[(size_t)(oy0 + threadIdx.y + j) * R + ox] = tile[threadIdx.x][threadIdx.y + j];
}

// ---------------- tf32 mma.sync GEMM ------------------------------------------
// Both operands K-major. A [M,K], B [N,K].
// MODE 0: g_xn @ Wt(which)^T -> q/k/v [z][s][d] (+bias, tf32 out)
// MODE 1: Q @ K^T * scale    -> g_scores (fp32; per z)
// MODE 2: P @ Vt^T           -> g_attn (tf32 out; per z)
// MODE 3: g_attn @ Wto^T     -> out (+bias, fp32)
template <int MODE>
__global__ __launch_bounds__(256, 2)
void gemm_tc(const float* __restrict__ bias, float* __restrict__ Cout, int which) {
    constexpr int K   = (MODE == 0) ? 512 : (MODE == 1) ? 512 : (MODE == 2) ? 2048 : 4096;
    constexpr int lda = (MODE == 2) ? 2048 : (MODE == 3) ? 4096 : 512;
    constexpr int ldb = (MODE == 2) ? 2048 : (MODE == 3) ? 4096 : 512;
    constexpr int T   = K / 16;

    // smem: [buf][row 0..127][20 floats] per operand; stride 20 -> conflict-free frags
    __shared__ float As[2][128][20];
    __shared__ float Bs[2][128][20];

    int tid = threadIdx.x;
    int lane = tid & 31, wid = tid >> 5;
    int warp_m = wid & 1, warp_n = wid >> 1;   // 2 x 4 warps -> 64 x 32 per warp
    int z = blockIdx.z;
    int m0 = blockIdx.y * 128, n0 = blockIdx.x * 128;

    const float* A;
    const float* Bm;
    if (MODE == 0)      { A = g_xn;
                          Bm = (which == 0) ? g_wtq : (which == 1) ? g_wtk : g_wtv; }
    else if (MODE == 1) { A = g_q + (size_t)z * S_ * D_; Bm = g_k + (size_t)z * S_ * D_; }
    else if (MODE == 2) { A = g_scores + ((size_t)z << 22); Bm = g_vt + (size_t)z * S_ * D_; }
    else                { A = g_attn; Bm = g_wto; }
    A  += (size_t)m0 * lda;
    Bm += (size_t)n0 * ldb;

    float c[4][4][4];
#pragma unroll
    for (int i = 0; i < 4; i++)
#pragma unroll
        for (int j = 0; j < 4; j++)
#pragma unroll
            for (int e = 0; e < 4; e++) c[i][j][e] = 0.0f;

    // cp.async tile loader: 512 float4 per operand, 2 per thread
    int ldr_row = tid >> 1;                 // 0..127 (two rows per... ) no: see below
    // mapping: j = tid + 256*i ; row = j>>2 ; seg = j&3
    uint32_t asb[2], bsb[2];
    asb[0] = smem_u32(&As[0][0][0]); asb[1] = smem_u32(&As[1][0][0]);
    bsb[0] = smem_u32(&Bs[0][0][0]); bsb[1] = smem_u32(&Bs[1][0][0]);
    (void)ldr_row;

    auto tile_load = [&](int buf, int k0) {
#pragma unroll
        for (int i = 0; i < 2; i++) {
            int j = tid + (i << 8);
            int row = j >> 2, seg = j & 3;
            cp16(asb[buf] + row * 80 + seg * 16, A + (size_t)row * lda + k0 + seg * 4);
            cp16(bsb[buf] + row * 80 + seg * 16, Bm + (size_t)row * ldb + k0 + seg * 4);
        }
        CP_COMMIT();
    };

    tile_load(0, 0);

    for (int t = 0; t < T; t++) {
        int buf = t & 1;
        if (t + 1 < T) { tile_load(buf ^ 1, (t + 1) * 16); CP_WAIT1(); }
        else           { CP_WAIT0(); }
        __syncthreads();

#pragma unroll
        for (int kf = 0; kf < 2; kf++) {
            uint32_t a[4][4], b[4][2];
            int ar = warp_m * 64 + (lane >> 2);
            int ac = kf * 8 + (lane & 3);
#pragma unroll
            for (int im = 0; im < 4; im++) {
                const float* p = &As[buf][ar + im * 16][ac];
                a[im][0] = __float_as_uint(p[0]);
                a[im][1] = __float_as_uint(p[8 * 20]);
                a[im][2] = __float_as_uint(p[4]);
                a[im][3] = __float_as_uint(p[8 * 20 + 4]);
            }
            int bn = warp_n * 32 + (lane >> 2);
#pragma unroll
            for (int jn = 0; jn < 4; jn++) {
                const float* p = &Bs[buf][bn + jn * 8][ac];
                b[jn][0] = __float_as_uint(p[0]);
                b[jn][1] = __float_as_uint(p[4]);
            }
#pragma unroll
            for (int im = 0; im < 4; im++)
#pragma unroll
                for (int jn = 0; jn < 4; jn++)
                    mma_tf32(c[im][jn], a[im], b[jn]);
        }
        __syncthreads();
    }

    // ---- epilogue: each thread owns float2 pairs at (r0, cc) and (r0+8, cc) ----
#pragma unroll
    for (int im = 0; im < 4; im++) {
#pragma unroll
        for (int jn = 0; jn < 4; jn++) {
            int r0 = m0 + warp_m * 64 + im * 16 + (lane >> 2);
            int cc = n0 + warp_n * 32 + jn * 8 + (lane & 3) * 2;
            float2 lo = make_float2(c[im][jn][0], c[im][jn][1]);
            float2 hi = make_float2(c[im][jn][2], c[im][jn][3]);

            if (MODE == 0) {
                float2 bv = *(const float2*)&bias[cc];
                lo.x = to_tf32(lo.x + bv.x); lo.y = to_tf32(lo.y + bv.y);
                hi.x = to_tf32(hi.x + bv.x); hi.y = to_tf32(hi.y + bv.y);
                float* C = (which == 0) ? g_q : (which == 1) ? g_k : g_v;
                int h = cc >> 9, d = cc & 511;
                int b0 = r0 >> 11, s0 = r0 & 2047;
                *(float2*)(C + ((size_t)(b0 * 8 + h) * S_ + s0) * D_ + d) = lo;
                int b1 = (r0 + 8) >> 11, s1 = (r0 + 8) & 2047;
                *(float2*)(C + ((size_t)(b1 * 8 + h) * S_ + s1) * D_ + d) = hi;
            } else if (MODE == 1) {
                lo.x *= ATT_SCALE; lo.y *= ATT_SCALE;
                hi.x *= ATT_SCALE; hi.y *= ATT_SCALE;
                float* base = g_scores + ((size_t)z << 22) + cc;
                *(float2*)(base + (size_t)r0 * S_) = lo;
                *(float2*)(base + (size_t)(r0 + 8) * S_) = hi;
            } else if (MODE == 2) {
                lo.x = to_tf32(lo.x); lo.y = to_tf32(lo.y);
                hi.x = to_tf32(hi.x); hi.y = to_tf32(hi.y);
                int b = z >> 3, h = z & 7;
                float* base = g_attn + (size_t)(b * S_) * DH + h * 512 + cc;
                *(float2*)(base + (size_t)r0 * DH) = lo;
                *(float2*)(base + (size_t)(r0 + 8) * DH) = hi;
            } else {
                float2 bv = *(const float2*)&bias[cc];
                lo.x += bv.x; lo.y += bv.y;
                hi.x += bv.x; hi.y += bv.y;
                *(float2*)(Cout + (size_t)r0 * D_ + cc) = lo;
                *(float2*)(Cout + (size_t)(r0 + 8) * D_ + cc) = hi;
            }
        }
    }
}

// ---------------- row softmax over 2048 (tf32-rounded output) -----------------
__global__ void softmax_kernel() {
    float4* rp = (float4*)(g_scores + ((size_t)blockIdx.x << 11));
    int t = threadIdx.x;                      // 256 threads
    float4 v0 = rp[t];
    float4 v1 = rp[t + 256];
    float mx = fmaxf(fmaxf(fmaxf(v0.x, v0.y), fmaxf(v0.z, v0.w)),
                     fmaxf(fmaxf(v1.x, v1.y), fmaxf(v1.z, v1.w)));
#pragma unroll
    for (int o = 16; o > 0; o >>= 1) mx = fmaxf(mx, __shfl_xor_sync(0xffffffffu, mx, o));
    __shared__ float sm[8];
    int w = t >> 5;
    if ((t & 31) == 0) sm[w] = mx;
    __syncthreads();
    mx = sm[0];
#pragma unroll
    for (int i = 1; i < 8; i++) mx = fmaxf(mx, sm[i]);

    v0.x = __expf(v0.x - mx); v0.y = __expf(v0.y - mx);
    v0.z = __expf(v0.z - mx); v0.w = __expf(v0.w - mx);
    v1.x = __expf(v1.x - mx); v1.y = __expf(v1.y - mx);
    v1.z = __expf(v1.z - mx); v1.w = __expf(v1.w - mx);
    float s = v0.x + v0.y + v0.z + v0.w + v1.x + v1.y + v1.z + v1.w;
#pragma unroll
    for (int o = 16; o > 0; o >>= 1) s += __shfl_xor_sync(0xffffffffu, s, o);
    __syncthreads();
    if ((t & 31) == 0) sm[w] = s;
    __syncthreads();
    s = sm[0] + sm[1] + sm[2] + sm[3] + sm[4] + sm[5] + sm[6] + sm[7];
    float inv = 1.0f / s;
    v0.x = to_tf32(v0.x * inv); v0.y = to_tf32(v0.y * inv);
    v0.z = to_tf32(v0.z * inv); v0.w = to_tf32(v0.w * inv);
    v1.x = to_tf32(v1.x * inv); v1.y = to_tf32(v1.y * inv);
    v1.z = to_tf32(v1.z * inv); v1.w = to_tf32(v1.w * inv);
    rp[t] = v0;
    rp[t + 256] = v1;
}

// ---------------- launch ------------------------------------------------------
extern "C" void kernel_launch(void* const* d_in, const int* in_sizes, int n_in,
                              void* d_out, int out_size) {
    const float* x    = (const float*)d_in[0];
    const float* ln_w = (const float*)d_in[1];
    const float* ln_b = (const float*)d_in[2];
    const float* q_w  = (const float*)d_in[3];
    const float* q_b  = (const float*)d_in[4];
    const float* k_w  = (const float*)d_in[5];
    const float* k_b  = (const float*)d_in[6];
    const float* v_w  = (const float*)d_in[7];
    const float* v_b  = (const float*)d_in[8];
    const float* o_w  = (const float*)d_in[9];
    const float* o_b  = (const float*)d_in[10];
    float* out = (float*)d_out;

    dim3 tb(32, 8);
    ln_kernel<<<NT, 128>>>(x, ln_w, ln_b);
    transpose_kernel<<<dim3(128, 16, 1), tb>>>(q_w, 0, 512, 4096);
    transpose_kernel<<<dim3(128, 16, 1), tb>>>(k_w, 1, 512, 4096);
    transpose_kernel<<<dim3(128, 16, 1), tb>>>(v_w, 2, 512, 4096);
    transpose_kernel<<<dim3(16, 128, 1), tb>>>(o_w, 3, 4096, 512);

    dim3 gQKV(DH / 128, NT / 128, 1);                      // (32, 64)
    gemm_tc<0><<<gQKV, 256>>>(q_b, nullptr, 0);
    gemm_tc<0><<<gQKV, 256>>>(k_b, nullptr, 1);
    gemm_tc<0><<<gQKV, 256>>>(v_b, nullptr, 2);

    // V transpose per z: [2048,512] -> [512,2048]
    transpose_kernel<<<dim3(16, 64, ZN), tb>>>(nullptr, 4, 2048, 512);

    dim3 gS(S_ / 128, S_ / 128, ZN);                       // (16, 16, 32)
    gemm_tc<1><<<gS, 256>>>(nullptr, nullptr, 0);

    softmax_kernel<<<ZN * S_, 256>>>();

    dim3 gPV(D_ / 128, S_ / 128, ZN);                      // (4, 16, 32)
    gemm_tc<2><<<gPV, 256>>>(nullptr, nullptr, 0);

    dim3 gO(D_ / 128, NT / 128, 1);                        // (4, 64)
    gemm_tc<3><<<gO, 256>>>(o_b, out, 0);
}

// round 4
// speedup vs baseline: 5.2143x; 1.9536x over previous
#include <cuda_runtime.h>
#include <cuda_fp16.h>
#include <cstdint>

// ---------------- problem constants ------------------------------------------
#define B_ 4
#define S_ 2048
#define D_ 512
#define H_ 8
#define NT 8192               // B*S tokens
#define DH 4096               // D*H
#define ZN 32                 // B*H attention instances
#define ATT_SCALE 0.04419417382415922f   // 512^-0.5

// ---------------- scratch (device globals; no runtime allocation) -------------
__device__ __half g_xn[(size_t)NT * D_];               // 8 MB
__device__ __half g_q[(size_t)ZN * S_ * D_];           // 64 MB [z][s][d] (pre-scaled)
__device__ __half g_k[(size_t)ZN * S_ * D_];           // 64 MB [z][s][d]
__device__ __half g_v[(size_t)ZN * S_ * D_];           // 64 MB [z][s][d]
__device__ __half g_vt[(size_t)ZN * S_ * D_];          // 64 MB [z][d][s]
__device__ float  g_scores[(size_t)ZN * S_ * S_];      // 512 MB fp32 logits
__device__ __half g_p[(size_t)ZN * S_ * S_];           // 256 MB fp16 probs
__device__ __half g_attn[(size_t)NT * DH];             // 64 MB [token][h*512+d]
__device__ __half g_wtq[(size_t)DH * D_];              // 4 MB  W^T [4096][512]
__device__ __half g_wtk[(size_t)DH * D_];
__device__ __half g_wtv[(size_t)DH * D_];
__device__ __half g_wto[(size_t)D_ * DH];              // 4 MB  o_w^T [512][4096]

// ---------------- helpers -----------------------------------------------------
__device__ __forceinline__ uint32_t smem_u32(const void* p) {
    uint32_t a;
    asm("{ .reg .u64 t; cvta.to.shared.u64 t, %1; cvt.u32.u64 %0, t; }" : "=r"(a) : "l"(p));
    return a;
}
__device__ __forceinline__ void cp16(uint32_t dst, const void* src) {
    asm volatile("cp.async.cg.shared.global [%0], [%1], 16;" :: "r"(dst), "l"(src));
}
#define CP_COMMIT() asm volatile("cp.async.commit_group;")
#define CP_WAIT1()  asm volatile("cp.async.wait_group 1;")
#define CP_WAIT0()  asm volatile("cp.async.wait_group 0;")

__device__ __forceinline__ void ldsm_x4(uint32_t* r, uint32_t addr) {
    asm volatile("ldmatrix.sync.aligned.m8n8.x4.shared.b16 {%0,%1,%2,%3}, [%4];"
        : "=r"(r[0]), "=r"(r[1]), "=r"(r[2]), "=r"(r[3]) : "r"(addr));
}
__device__ __forceinline__ void mma_f16(float* c, const uint32_t* a, const uint32_t* b) {
    asm volatile(
        "mma.sync.aligned.m16n8k16.row.col.f32.f16.f16.f32 "
        "{%0,%1,%2,%3}, {%4,%5,%6,%7}, {%8,%9}, {%0,%1,%2,%3};"
        : "+f"(c[0]), "+f"(c[1]), "+f"(c[2]), "+f"(c[3])
        : "r"(a[0]), "r"(a[1]), "r"(a[2]), "r"(a[3]), "r"(b[0]), "r"(b[1]));
}

// ---------------- LayerNorm (fp32 in -> fp16 out) -----------------------------
__global__ void ln_kernel(const float* __restrict__ x,
                          const float* __restrict__ w,
                          const float* __restrict__ b) {
    int row = blockIdx.x;
    int t = threadIdx.x;                       // 128 threads, 4 floats each
    const float4* xr = (const float4*)(x + (size_t)row * D_);
    float4 v = xr[t];
    float s  = v.x + v.y + v.z + v.w;
    float q  = v.x * v.x + v.y * v.y + v.z * v.z + v.w * v.w;
#pragma unroll
    for (int o = 16; o > 0; o >>= 1) {
        s += __shfl_xor_sync(0xffffffffu, s, o);
        q += __shfl_xor_sync(0xffffffffu, q, o);
    }
    __shared__ float ss[4], sq[4];
    int wid = t >> 5;
    if ((t & 31) == 0) { ss[wid] = s; sq[wid] = q; }
    __syncthreads();
    s = ss[0] + ss[1] + ss[2] + ss[3];
    q = sq[0] + sq[1] + sq[2] + sq[3];
    float mu  = s * (1.0f / D_);
    float var = q * (1.0f / D_) - mu * mu;
    float r   = rsqrtf(var + 1e-5f);
    float4 wv = ((const float4*)w)[t];
    float4 bv = ((const float4*)b)[t];
    __half2 h0 = __floats2half2_rn((v.x - mu) * r * wv.x + bv.x,
                                   (v.y - mu) * r * wv.y + bv.y);
    __half2 h1 = __floats2half2_rn((v.z - mu) * r * wv.z + bv.z,
                                   (v.w - mu) * r * wv.w + bv.w);
    __half2* dst = (__half2*)(g_xn + (size_t)row * D_);
    dst[2 * t]     = h0;
    dst[2 * t + 1] = h1;
}

// ---------------- 32x32 tiled transpose ---------------------------------------
// sel 0..3: fp32 weights in -> half out. sel 4: half V -> half Vt per z.
__global__ void transpose_kernel(const float* __restrict__ in_f32, int sel, int R, int C) {
    __shared__ float tile[32][33];
    int z = blockIdx.z;
    __half* out;
    const __half* in_h = nullptr;
    if (sel == 0)      out = g_wtq;
    else if (sel == 1) out = g_wtk;
    else if (sel == 2) out = g_wtv;
    else if (sel == 3) out = g_wto;
    else { in_h = g_v + (size_t)z * S_ * D_; out = g_vt + (size_t)z * S_ * D_; }

    int x  = blockIdx.x * 32 + threadIdx.x;
    int y0 = blockIdx.y * 32;
#pragma unroll
    for (int j = 0; j < 32; j += 8) {
        float v;
        if (sel < 4) v = in_f32[(size_t)(y0 + threadIdx.y + j) * C + x];
        else         v = __half2float(in_h[(size_t)(y0 + threadIdx.y + j) * C + x]);
        tile[threadIdx.y + j][threadIdx.x] = v;
    }
    __syncthreads();
    int ox  = y0 + threadIdx.x;
    int oy0 = blockIdx.x * 32;
#pragma unroll
    for (int j = 0; j < 32; j += 8)
        out[(size_t)(oy0 + threadIdx.y + j) * R + ox] =
            __float2half_rn(tile[threadIdx.x][threadIdx.y + j]);
}

// ---------------- fp16 mma.sync GEMM ------------------------------------------
// Both operands K-major fp16. A [M,K], B [N,K]. fp32 accumulate.
// MODE 0: g_xn @ Wt(which)^T -> q(/scale)/k/v half (+bias)
// MODE 1: Qs @ K^T           -> g_scores fp32 (per z)
// MODE 2: P @ Vt^T           -> g_attn half (per z)
// MODE 3: g_attn @ Wto^T     -> out fp32 (+bias)
template <int MODE>
__global__ __launch_bounds__(256, 2)
void gemm_tc(const float* __restrict__ bias, float* __restrict__ Cout, int which) {
    constexpr int K   = (MODE == 0) ? 512 : (MODE == 1) ? 512 : (MODE == 2) ? 2048 : 4096;
    constexpr int lda = (MODE == 2) ? 2048 : (MODE == 3) ? 4096 : 512;
    constexpr int ldb = (MODE == 2) ? 2048 : (MODE == 3) ? 4096 : 512;
    constexpr int T   = K / 32;

    // rows padded to 40 halves (80B) -> conflict-free ldmatrix
    __shared__ __half As[2][128][40];
    __shared__ __half Bs[2][128][40];

    int tid = threadIdx.x;
    int lane = tid & 31, wid = tid >> 5;
    int warp_m = wid & 1, warp_n = wid >> 1;   // 2 x 4 warps -> 64 x 32 per warp
    int z = blockIdx.z;
    int m0 = blockIdx.y * 128, n0 = blockIdx.x * 128;

    const __half* A;
    const __half* Bm;
    if (MODE == 0)      { A = g_xn;
                          Bm = (which == 0) ? g_wtq : (which == 1) ? g_wtk : g_wtv; }
    else if (MODE == 1) { A = g_q + (size_t)z * S_ * D_; Bm = g_k + (size_t)z * S_ * D_; }
    else if (MODE == 2) { A = g_p + ((size_t)z << 22);   Bm = g_vt + (size_t)z * S_ * D_; }
    else                { A = g_attn; Bm = g_wto; }
    A  += (size_t)m0 * lda;
    Bm += (size_t)n0 * ldb;

    float c[4][4][4];
#pragma unroll
    for (int i = 0; i < 4; i++)
#pragma unroll
        for (int j = 0; j < 4; j++)
#pragma unroll
            for (int e = 0; e < 4; e++) c[i][j][e] = 0.0f;

    uint32_t asb[2], bsb[2];
    asb[0] = smem_u32(&As[0][0][0]); asb[1] = smem_u32(&As[1][0][0]);
    bsb[0] = smem_u32(&Bs[0][0][0]); bsb[1] = smem_u32(&Bs[1][0][0]);

    // tile fill: 128 rows x 32 halves (64B) per operand = 512 x 16B; 2 per thread
    auto tile_load = [&](int buf, int k0) {
#pragma unroll
        for (int i = 0; i < 2; i++) {
            int j = tid + (i << 8);
            int row = j >> 2, seg = j & 3;
            cp16(asb[buf] + row * 80 + seg * 16, A + (size_t)row * lda + k0 + seg * 8);
            cp16(bsb[buf] + row * 80 + seg * 16, Bm + (size_t)row * ldb + k0 + seg * 8);
        }
        CP_COMMIT();
    };

    // ldmatrix lane geometry (byte offsets within a buffer)
    int rowA = warp_m * 64 + (lane & 7) + ((lane & 8) ? 8 : 0);
    int kA   = (lane & 16) ? 8 : 0;
    int rowB = warp_n * 32 + (lane & 7) + ((lane & 16) ? 8 : 0);
    int kB   = (lane & 8) ? 8 : 0;

    tile_load(0, 0);

    for (int t = 0; t < T; t++) {
        int buf = t & 1;
        if (t + 1 < T) { tile_load(buf ^ 1, (t + 1) * 32); CP_WAIT1(); }
        else           { CP_WAIT0(); }
        __syncthreads();

#pragma unroll
        for (int kf = 0; kf < 2; kf++) {
            uint32_t a[4][4], b[2][4];
#pragma unroll
            for (int im = 0; im < 4; im++)
                ldsm_x4(a[im], asb[buf] + (uint32_t)(rowA + im * 16) * 80
                                        + (uint32_t)(kA + kf * 16) * 2);
#pragma unroll
            for (int jp = 0; jp < 2; jp++)
                ldsm_x4(b[jp], bsb[buf] + (uint32_t)(rowB + jp * 16) * 80
                                        + (uint32_t)(kB + kf * 16) * 2);
#pragma unroll
            for (int im = 0; im < 4; im++)
#pragma unroll
                for (int jn = 0; jn < 4; jn++)
                    mma_f16(c[im][jn], a[im], &b[jn >> 1][(jn & 1) * 2]);
        }
        __syncthreads();
    }

    // ---- epilogue: thread owns cols (cc, cc+1) at rows r0 and r0+8 ----
#pragma unroll
    for (int im = 0; im < 4; im++) {
#pragma unroll
        for (int jn = 0; jn < 4; jn++) {
            int r0 = m0 + warp_m * 64 + im * 16 + (lane >> 2);
            int cc = n0 + warp_n * 32 + jn * 8 + (lane & 3) * 2;
            float2 lo = make_float2(c[im][jn][0], c[im][jn][1]);
            float2 hi = make_float2(c[im][jn][2], c[im][jn][3]);

            if (MODE == 0) {
                float2 bv = *(const float2*)&bias[cc];
                lo.x += bv.x; lo.y += bv.y;
                hi.x += bv.x; hi.y += bv.y;
                if (which == 0) {   // pre-scale Q
                    lo.x *= ATT_SCALE; lo.y *= ATT_SCALE;
                    hi.x *= ATT_SCALE; hi.y *= ATT_SCALE;
                }
                __half* C = (which == 0) ? g_q : (which == 1) ? g_k : g_v;
                int h = cc >> 9, d = cc & 511;
                int b0 = r0 >> 11, s0 = r0 & 2047;
                *(__half2*)(C + ((size_t)(b0 * 8 + h) * S_ + s0) * D_ + d) =
                    __floats2half2_rn(lo.x, lo.y);
                int b1 = (r0 + 8) >> 11, s1 = (r0 + 8) & 2047;
                *(__half2*)(C + ((size_t)(b1 * 8 + h) * S_ + s1) * D_ + d) =
                    __floats2half2_rn(hi.x, hi.y);
            } else if (MODE == 1) {
                float* base = g_scores + ((size_t)z << 22) + cc;
                *(float2*)(base + (size_t)r0 * S_) = lo;
                *(float2*)(base + (size_t)(r0 + 8) * S_) = hi;
            } else if (MODE == 2) {
                int b = z >> 3, h = z & 7;
                __half* base = g_attn + (size_t)(b * S_) * DH + h * 512 + cc;
                *(__half2*)(base + (size_t)r0 * DH) = __floats2half2_rn(lo.x, lo.y);
                *(__half2*)(base + (size_t)(r0 + 8) * DH) = __floats2half2_rn(hi.x, hi.y);
            } else {
                float2 bv = *(const float2*)&bias[cc];
                lo.x += bv.x; lo.y += bv.y;
                hi.x += bv.x; hi.y += bv.y;
                *(float2*)(Cout + (size_t)r0 * D_ + cc) = lo;
                *(float2*)(Cout + (size_t)(r0 + 8) * D_ + cc) = hi;
            }
        }
    }
}

// ---------------- row softmax: fp32 logits -> fp16 probs ----------------------
__global__ void softmax_kernel() {
    const float4* rp = (const float4*)(g_scores + ((size_t)blockIdx.x << 11));
    __half* prow = g_p + ((size_t)blockIdx.x << 11);
    int t = threadIdx.x;                      // 256 threads, 8 floats each
    float4 v0 = rp[t];
    float4 v1 = rp[t + 256];
    float mx = fmaxf(fmaxf(fmaxf(v0.x, v0.y), fmaxf(v0.z, v0.w)),
                     fmaxf(fmaxf(v1.x, v1.y), fmaxf(v1.z, v1.w)));
#pragma unroll
    for (int o = 16; o > 0; o >>= 1) mx = fmaxf(mx, __shfl_xor_sync(0xffffffffu, mx, o));
    __shared__ float sm[8];
    int w = t >> 5;
    if ((t & 31) == 0) sm[w] = mx;
    __syncthreads();
    mx = sm[0];
#pragma unroll
    for (int i = 1; i < 8; i++) mx = fmaxf(mx, sm[i]);

    v0.x = __expf(v0.x - mx); v0.y = __expf(v0.y - mx);
    v0.z = __expf(v0.z - mx); v0.w = __expf(v0.w - mx);
    v1.x = __expf(v1.x - mx); v1.y = __expf(v1.y - mx);
    v1.z = __expf(v1.z - mx); v1.w = __expf(v1.w - mx);
    float s = v0.x + v0.y + v0.z + v0.w + v1.x + v1.y + v1.z + v1.w;
#pragma unroll
    for (int o = 16; o > 0; o >>= 1) s += __shfl_xor_sync(0xffffffffu, s, o);
    __syncthreads();
    if ((t & 31) == 0) sm[w] = s;
    __syncthreads();
    s = sm[0] + sm[1] + sm[2] + sm[3] + sm[4] + sm[5] + sm[6] + sm[7];
    float inv = 1.0f / s;
    __half2* pp = (__half2*)prow;
    pp[2 * t]           = __floats2half2_rn(v0.x * inv, v0.y * inv);
    pp[2 * t + 1]       = __floats2half2_rn(v0.z * inv, v0.w * inv);
    pp[2 * (t + 256)]     = __floats2half2_rn(v1.x * inv, v1.y * inv);
    pp[2 * (t + 256) + 1] = __floats2half2_rn(v1.z * inv, v1.w * inv);
}

// ---------------- launch ------------------------------------------------------
extern "C" void kernel_launch(void* const* d_in, const int* in_sizes, int n_in,
                              void* d_out, int out_size) {
    const float* x    = (const float*)d_in[0];
    const float* ln_w = (const float*)d_in[1];
    const float* ln_b = (const float*)d_in[2];
    const float* q_w  = (const float*)d_in[3];
    const float* q_b  = (const float*)d_in[4];
    const float* k_w  = (const float*)d_in[5];
    const float* k_b  = (const float*)d_in[6];
    const float* v_w  = (const float*)d_in[7];
    const float* v_b  = (const float*)d_in[8];
    const float* o_w  = (const float*)d_in[9];
    const float* o_b  = (const float*)d_in[10];
    float* out = (float*)d_out;

    dim3 tb(32, 8);
    ln_kernel<<<NT, 128>>>(x, ln_w, ln_b);
    transpose_kernel<<<dim3(128, 16, 1), tb>>>(q_w, 0, 512, 4096);
    transpose_kernel<<<dim3(128, 16, 1), tb>>>(k_w, 1, 512, 4096);
    transpose_kernel<<<dim3(128, 16, 1), tb>>>(v_w, 2, 512, 4096);
    transpose_kernel<<<dim3(16, 128, 1), tb>>>(o_w, 3, 4096, 512);

    dim3 gQKV(DH / 128, NT / 128, 1);                      // (32, 64)
    gemm_tc<0><<<gQKV, 256>>>(q_b, nullptr, 0);
    gemm_tc<0><<<gQKV, 256>>>(k_b, nullptr, 1);
    gemm_tc<0><<<gQKV, 256>>>(v_b, nullptr, 2);

    // V transpose per z: [2048,512] -> [512,2048]
    transpose_kernel<<<dim3(16, 64, ZN), tb>>>(nullptr, 4, 2048, 512);

    dim3 gS(S_ / 128, S_ / 128, ZN);                       // (16, 16, 32)
    gemm_tc<1><<<gS, 256>>>(nullptr, nullptr, 0);

    softmax_kernel<<<ZN * S_, 256>>>();

    dim3 gPV(D_ / 128, S_ / 128, ZN);                      // (4, 16, 32)
    gemm_tc<2><<<gPV, 256>>>(nullptr, nullptr, 0);

    dim3 gO(D_ / 128, NT / 128, 1);                        // (4, 64)
    gemm_tc<3><<<gO, 256>>>(o_b, out, 0);
}

// round 5
// speedup vs baseline: 6.0100x; 1.1526x over previous
#include <cuda_runtime.h>
#include <cuda_fp16.h>
#include <cstdint>

// ---------------- problem constants ------------------------------------------
#define B_ 4
#define S_ 2048
#define D_ 512
#define H_ 8
#define NT 8192               // B*S tokens
#define DH 4096               // D*H
#define ZN 32                 // B*H attention instances
#define ATT_SCALE 0.04419417382415922f   // 512^-0.5

// ---------------- scratch (device globals; no runtime allocation) -------------
__device__ __half g_xn[(size_t)NT * D_];               // 8 MB
__device__ __half g_q[(size_t)ZN * S_ * D_];           // 64 MB [z][s][d] (pre-scaled)
__device__ __half g_k[(size_t)ZN * S_ * D_];           // 64 MB [z][s][d]
__device__ __half g_v[(size_t)ZN * S_ * D_];           // 64 MB [z][s][d]
__device__ __half g_vt[(size_t)ZN * S_ * D_];          // 64 MB [z][d][s]
__device__ float  g_scores[(size_t)ZN * S_ * S_];      // 512 MB fp32 logits
__device__ __half g_p[(size_t)ZN * S_ * S_];           // 256 MB fp16 probs
__device__ __half g_attn[(size_t)NT * DH];             // 64 MB [token][h*512+d]
__device__ __half g_wtq[(size_t)DH * D_];              // 4 MB  W^T [4096][512]
__device__ __half g_wtk[(size_t)DH * D_];
__device__ __half g_wtv[(size_t)DH * D_];
__device__ __half g_wto[(size_t)D_ * DH];              // 4 MB  o_w^T [512][4096]

// ---------------- helpers -----------------------------------------------------
__device__ __forceinline__ uint32_t smem_u32(const void* p) {
    uint32_t a;
    asm("{ .reg .u64 t; cvta.to.shared.u64 t, %1; cvt.u32.u64 %0, t; }" : "=r"(a) : "l"(p));
    return a;
}
__device__ __forceinline__ void cp16(uint32_t dst, const void* src) {
    asm volatile("cp.async.cg.shared.global [%0], [%1], 16;" :: "r"(dst), "l"(src));
}
#define CP_COMMIT() asm volatile("cp.async.commit_group;")
#define CP_WAIT1()  asm volatile("cp.async.wait_group 1;")

__device__ __forceinline__ void ldsm_x4(uint32_t* r, uint32_t addr) {
    asm volatile("ldmatrix.sync.aligned.m8n8.x4.shared.b16 {%0,%1,%2,%3}, [%4];"
        : "=r"(r[0]), "=r"(r[1]), "=r"(r[2]), "=r"(r[3]) : "r"(addr));
}
__device__ __forceinline__ void mma_f16(float* c, const uint32_t* a, const uint32_t* b) {
    asm volatile(
        "mma.sync.aligned.m16n8k16.row.col.f32.f16.f16.f32 "
        "{%0,%1,%2,%3}, {%4,%5,%6,%7}, {%8,%9}, {%0,%1,%2,%3};"
        : "+f"(c[0]), "+f"(c[1]), "+f"(c[2]), "+f"(c[3])
        : "r"(a[0]), "r"(a[1]), "r"(a[2]), "r"(a[3]), "r"(b[0]), "r"(b[1]));
}

// ---------------- LayerNorm (fp32 in -> fp16 out) -----------------------------
__global__ void ln_kernel(const float* __restrict__ x,
                          const float* __restrict__ w,
                          const float* __restrict__ b) {
    int row = blockIdx.x;
    int t = threadIdx.x;                       // 128 threads, 4 floats each
    const float4* xr = (const float4*)(x + (size_t)row * D_);
    float4 v = xr[t];
    float s  = v.x + v.y + v.z + v.w;
    float q  = v.x * v.x + v.y * v.y + v.z * v.z + v.w * v.w;
#pragma unroll
    for (int o = 16; o > 0; o >>= 1) {
        s += __shfl_xor_sync(0xffffffffu, s, o);
        q += __shfl_xor_sync(0xffffffffu, q, o);
    }
    __shared__ float ss[4], sq[4];
    int wid = t >> 5;
    if ((t & 31) == 0) { ss[wid] = s; sq[wid] = q; }
    __syncthreads();
    s = ss[0] + ss[1] + ss[2] + ss[3];
    q = sq[0] + sq[1] + sq[2] + sq[3];
    float mu  = s * (1.0f / D_);
    float var = q * (1.0f / D_) - mu * mu;
    float r   = rsqrtf(var + 1e-5f);
    float4 wv = ((const float4*)w)[t];
    float4 bv = ((const float4*)b)[t];
    __half2 h0 = __floats2half2_rn((v.x - mu) * r * wv.x + bv.x,
                                   (v.y - mu) * r * wv.y + bv.y);
    __half2 h1 = __floats2half2_rn((v.z - mu) * r * wv.z + bv.z,
                                   (v.w - mu) * r * wv.w + bv.w);
    __half2* dst = (__half2*)(g_xn + (size_t)row * D_);
    dst[2 * t]     = h0;
    dst[2 * t + 1] = h1;
}

// ---------------- 32x32 tiled transpose ---------------------------------------
// sel 0..3: fp32 weights in -> half out. sel 4: half V -> half Vt per z.
__global__ void transpose_kernel(const float* __restrict__ in_f32, int sel, int R, int C) {
    __shared__ float tile[32][33];
    int z = blockIdx.z;
    __half* out;
    const __half* in_h = nullptr;
    if (sel == 0)      out = g_wtq;
    else if (sel == 1) out = g_wtk;
    else if (sel == 2) out = g_wtv;
    else if (sel == 3) out = g_wto;
    else { in_h = g_v + (size_t)z * S_ * D_; out = g_vt + (size_t)z * S_ * D_; }

    int x  = blockIdx.x * 32 + threadIdx.x;
    int y0 = blockIdx.y * 32;
#pragma unroll
    for (int j = 0; j < 32; j += 8) {
        float v;
        if (sel < 4) v = in_f32[(size_t)(y0 + threadIdx.y + j) * C + x];
        else         v = __half2float(in_h[(size_t)(y0 + threadIdx.y + j) * C + x]);
        tile[threadIdx.y + j][threadIdx.x] = v;
    }
    __syncthreads();
    int ox  = y0 + threadIdx.x;
    int oy0 = blockIdx.x * 32;
#pragma unroll
    for (int j = 0; j < 32; j += 8)
        out[(size_t)(oy0 + threadIdx.y + j) * R + ox] =
            __float2half_rn(tile[threadIdx.x][threadIdx.y + j]);
}

// ---------------- fp16 mma.sync GEMM, 3-stage cp.async pipeline ---------------
// Both operands K-major fp16. A [M,K], B [N,K]. fp32 accumulate.
// MODE 0: g_xn @ Wt(which)^T -> q(/scale)/k/v half (+bias)
// MODE 1: Qs @ K^T           -> g_scores fp32 (per z)
// MODE 2: P @ Vt^T           -> g_attn half (per z)
// MODE 3: g_attn @ Wto^T     -> out fp32 (+bias)
constexpr int STG = 3;
constexpr int OPBYTES = 128 * 40 * 2;            // one operand tile: 10240 B
constexpr int STGBYTES = 2 * OPBYTES;            // A+B per stage: 20480 B
constexpr int GEMM_SMEM = STG * STGBYTES;        // 61440 B

template <int MODE>
__global__ __launch_bounds__(256, 2)
void gemm_tc(const float* __restrict__ bias, float* __restrict__ Cout, int which) {
    constexpr int K   = (MODE == 0) ? 512 : (MODE == 1) ? 512 : (MODE == 2) ? 2048 : 4096;
    constexpr int lda = (MODE == 2) ? 2048 : (MODE == 3) ? 4096 : 512;
    constexpr int ldb = (MODE == 2) ? 2048 : (MODE == 3) ? 4096 : 512;
    constexpr int T   = K / 32;

    extern __shared__ __half sh[];
    uint32_t sbase = smem_u32(sh);

    int tid = threadIdx.x;
    int lane = tid & 31, wid = tid >> 5;
    int warp_m = wid & 1, warp_n = wid >> 1;   // 2 x 4 warps -> 64 x 32 per warp
    int z = blockIdx.z;
    int m0 = blockIdx.y * 128, n0 = blockIdx.x * 128;

    const __half* A;
    const __half* Bm;
    if (MODE == 0)      { A = g_xn;
                          Bm = (which == 0) ? g_wtq : (which == 1) ? g_wtk : g_wtv; }
    else if (MODE == 1) { A = g_q + (size_t)z * S_ * D_; Bm = g_k + (size_t)z * S_ * D_; }
    else if (MODE == 2) { A = g_p + ((size_t)z << 22);   Bm = g_vt + (size_t)z * S_ * D_; }
    else                { A = g_attn; Bm = g_wto; }
    A  += (size_t)m0 * lda;
    Bm += (size_t)n0 * ldb;

    float c[4][4][4];
#pragma unroll
    for (int i = 0; i < 4; i++)
#pragma unroll
        for (int j = 0; j < 4; j++)
#pragma unroll
            for (int e = 0; e < 4; e++) c[i][j][e] = 0.0f;

    // tile fill: 128 rows x 32 halves (64B) per operand = 512 x 16B; 2 per thread
    int lrow = tid >> 2, lseg = tid & 3;       // first half; second adds 64 rows
    auto tile_load = [&](int stg, int k0) {
        uint32_t abase = sbase + (uint32_t)stg * STGBYTES;
#pragma unroll
        for (int i = 0; i < 2; i++) {
            int row = lrow + i * 64;
            uint32_t off = (uint32_t)row * 80 + (uint32_t)lseg * 16;
            cp16(abase + off,           A  + (size_t)row * lda + k0 + lseg * 8);
            cp16(abase + OPBYTES + off, Bm + (size_t)row * ldb + k0 + lseg * 8);
        }
        CP_COMMIT();
    };

    // ldmatrix lane geometry (byte offsets within one operand tile)
    int rowA = warp_m * 64 + (lane & 7) + ((lane & 8) ? 8 : 0);
    int kA   = (lane & 16) ? 8 : 0;
    int rowB = warp_n * 32 + (lane & 7) + ((lane & 16) ? 8 : 0);
    int kB   = (lane & 8) ? 8 : 0;

    // prologue: prefetch STG-1 tiles
    tile_load(0, 0);
    tile_load(1, 32);

    for (int t = 0; t < T; t++) {
        int buf = t % STG;
        CP_WAIT1();                 // stage t landed (tail commits are empty groups)
        __syncthreads();            // all warps done with stage t-1's buffer
        {
            int tn = t + STG - 1;
            if (tn < T) tile_load(tn % STG, tn * 32);
            else        CP_COMMIT();      // empty group keeps the wait count aligned
        }

        uint32_t abase = sbase + (uint32_t)buf * STGBYTES;
        uint32_t bbase = abase + OPBYTES;
#pragma unroll
        for (int kf = 0; kf < 2; kf++) {
            uint32_t a[4][4], b[2][4];
#pragma unroll
            for (int im = 0; im < 4; im++)
                ldsm_x4(a[im], abase + (uint32_t)(rowA + im * 16) * 80
                                     + (uint32_t)(kA + kf * 16) * 2);
#pragma unroll
            for (int jp = 0; jp < 2; jp++)
                ldsm_x4(b[jp], bbase + (uint32_t)(rowB + jp * 16) * 80
                                     + (uint32_t)(kB + kf * 16) * 2);
#pragma unroll
            for (int im = 0; im < 4; im++)
#pragma unroll
                for (int jn = 0; jn < 4; jn++)
                    mma_f16(c[im][jn], a[im], &b[jn >> 1][(jn & 1) * 2]);
        }
    }
    __syncthreads();

    // ---- epilogue: thread owns cols (cc, cc+1) at rows r0 and r0+8 ----
#pragma unroll
    for (int im = 0; im < 4; im++) {
#pragma unroll
        for (int jn = 0; jn < 4; jn++) {
            int r0 = m0 + warp_m * 64 + im * 16 + (lane >> 2);
            int cc = n0 + warp_n * 32 + jn * 8 + (lane & 3) * 2;
            float2 lo = make_float2(c[im][jn][0], c[im][jn][1]);
            float2 hi = make_float2(c[im][jn][2], c[im][jn][3]);

            if (MODE == 0) {
                float2 bv = *(const float2*)&bias[cc];
                lo.x += bv.x; lo.y += bv.y;
                hi.x += bv.x; hi.y += bv.y;
                if (which == 0) {   // pre-scale Q
                    lo.x *= ATT_SCALE; lo.y *= ATT_SCALE;
                    hi.x *= ATT_SCALE; hi.y *= ATT_SCALE;
                }
                __half* C = (which == 0) ? g_q : (which == 1) ? g_k : g_v;
                int h = cc >> 9, d = cc & 511;
                int b0 = r0 >> 11, s0 = r0 & 2047;
                *(__half2*)(C + ((size_t)(b0 * 8 + h) * S_ + s0) * D_ + d) =
                    __floats2half2_rn(lo.x, lo.y);
                int b1 = (r0 + 8) >> 11, s1 = (r0 + 8) & 2047;
                *(__half2*)(C + ((size_t)(b1 * 8 + h) * S_ + s1) * D_ + d) =
                    __floats2half2_rn(hi.x, hi.y);
            } else if (MODE == 1) {
                float* base = g_scores + ((size_t)z << 22) + cc;
                *(float2*)(base + (size_t)r0 * S_) = lo;
                *(float2*)(base + (size_t)(r0 + 8) * S_) = hi;
            } else if (MODE == 2) {
                int b = z >> 3, h = z & 7;
                __half* base = g_attn + (size_t)(b * S_) * DH + h * 512 + cc;
                *(__half2*)(base + (size_t)r0 * DH) = __floats2half2_rn(lo.x, lo.y);
                *(__half2*)(base + (size_t)(r0 + 8) * DH) = __floats2half2_rn(hi.x, hi.y);
            } else {
                float2 bv = *(const float2*)&bias[cc];
                lo.x += bv.x; lo.y += bv.y;
                hi.x += bv.x; hi.y += bv.y;
                *(float2*)(Cout + (size_t)r0 * D_ + cc) = lo;
                *(float2*)(Cout + (size_t)(r0 + 8) * D_ + cc) = hi;
            }
        }
    }
}

// ---------------- row softmax: fp32 logits -> fp16 probs ----------------------
__global__ void softmax_kernel() {
    const float4* rp = (const float4*)(g_scores + ((size_t)blockIdx.x << 11));
    __half* prow = g_p + ((size_t)blockIdx.x << 11);
    int t = threadIdx.x;                      // 256 threads, 8 floats each
    float4 v0 = rp[t];
    float4 v1 = rp[t + 256];
    float mx = fmaxf(fmaxf(fmaxf(v0.x, v0.y), fmaxf(v0.z, v0.w)),
                     fmaxf(fmaxf(v1.x, v1.y), fmaxf(v1.z, v1.w)));
#pragma unroll
    for (int o = 16; o > 0; o >>= 1) mx = fmaxf(mx, __shfl_xor_sync(0xffffffffu, mx, o));
    __shared__ float sm[8];
    int w = t >> 5;
    if ((t & 31) == 0) sm[w] = mx;
    __syncthreads();
    mx = sm[0];
#pragma unroll
    for (int i = 1; i < 8; i++) mx = fmaxf(mx, sm[i]);

    v0.x = __expf(v0.x - mx); v0.y = __expf(v0.y - mx);
    v0.z = __expf(v0.z - mx); v0.w = __expf(v0.w - mx);
    v1.x = __expf(v1.x - mx); v1.y = __expf(v1.y - mx);
    v1.z = __expf(v1.z - mx); v1.w = __expf(v1.w - mx);
    float s = v0.x + v0.y + v0.z + v0.w + v1.x + v1.y + v1.z + v1.w;
#pragma unroll
    for (int o = 16; o > 0; o >>= 1) s += __shfl_xor_sync(0xffffffffu, s, o);
    __syncthreads();
    if ((t & 31) == 0) sm[w] = s;
    __syncthreads();
    s = sm[0] + sm[1] + sm[2] + sm[3] + sm[4] + sm[5] + sm[6] + sm[7];
    float inv = 1.0f / s;
    __half2* pp = (__half2*)prow;
    pp[2 * t]             = __floats2half2_rn(v0.x * inv, v0.y * inv);
    pp[2 * t + 1]         = __floats2half2_rn(v0.z * inv, v0.w * inv);
    pp[2 * (t + 256)]     = __floats2half2_rn(v1.x * inv, v1.y * inv);
    pp[2 * (t + 256) + 1] = __floats2half2_rn(v1.z * inv, v1.w * inv);
}

// ---------------- launch ------------------------------------------------------
extern "C" void kernel_launch(void* const* d_in, const int* in_sizes, int n_in,
                              void* d_out, int out_size) {
    const float* x    = (const float*)d_in[0];
    const float* ln_w = (const float*)d_in[1];
    const float* ln_b = (const float*)d_in[2];
    const float* q_w  = (const float*)d_in[3];
    const float* q_b  = (const float*)d_in[4];
    const float* k_w  = (const float*)d_in[5];
    const float* k_b  = (const float*)d_in[6];
    const float* v_w  = (const float*)d_in[7];
    const float* v_b  = (const float*)d_in[8];
    const float* o_w  = (const float*)d_in[9];
    const float* o_b  = (const float*)d_in[10];
    float* out = (float*)d_out;

    static bool attr_done = false;
    if (!attr_done) {
        cudaFuncSetAttribute(gemm_tc<0>, cudaFuncAttributeMaxDynamicSharedMemorySize, GEMM_SMEM);
        cudaFuncSetAttribute(gemm_tc<1>, cudaFuncAttributeMaxDynamicSharedMemorySize, GEMM_SMEM);
        cudaFuncSetAttribute(gemm_tc<2>, cudaFuncAttributeMaxDynamicSharedMemorySize, GEMM_SMEM);
        cudaFuncSetAttribute(gemm_tc<3>, cudaFuncAttributeMaxDynamicSharedMemorySize, GEMM_SMEM);
        attr_done = true;
    }

    dim3 tb(32, 8);
    ln_kernel<<<NT, 128>>>(x, ln_w, ln_b);
    transpose_kernel<<<dim3(128, 16, 1), tb>>>(q_w, 0, 512, 4096);
    transpose_kernel<<<dim3(128, 16, 1), tb>>>(k_w, 1, 512, 4096);
    transpose_kernel<<<dim3(128, 16, 1), tb>>>(v_w, 2, 512, 4096);
    transpose_kernel<<<dim3(16, 128, 1), tb>>>(o_w, 3, 4096, 512);

    dim3 gQKV(DH / 128, NT / 128, 1);                      // (32, 64)
    gemm_tc<0><<<gQKV, 256, GEMM_SMEM>>>(q_b, nullptr, 0);
    gemm_tc<0><<<gQKV, 256, GEMM_SMEM>>>(k_b, nullptr, 1);
    gemm_tc<0><<<gQKV, 256, GEMM_SMEM>>>(v_b, nullptr, 2);

    // V transpose per z: [2048,512] -> [512,2048]
    transpose_kernel<<<dim3(16, 64, ZN), tb>>>(nullptr, 4, 2048, 512);

    dim3 gS(S_ / 128, S_ / 128, ZN);                       // (16, 16, 32)
    gemm_tc<1><<<gS, 256, GEMM_SMEM>>>(nullptr, nullptr, 0);

    softmax_kernel<<<ZN * S_, 256>>>();

    dim3 gPV(D_ / 128, S_ / 128, ZN);                      // (4, 16, 32)
    gemm_tc<2><<<gPV, 256, GEMM_SMEM>>>(nullptr, nullptr, 0);

    dim3 gO(D_ / 128, NT / 128, 1);                        // (4, 64)
    gemm_tc<3><<<gO, 256, GEMM_SMEM>>>(o_b, out, 0);
}

// round 6
// speedup vs baseline: 6.2774x; 1.0445x over previous
#include <cuda_runtime.h>
#include <cuda_fp16.h>
#include <cstdint>

// ---------------- problem constants ------------------------------------------
#define B_ 4
#define S_ 2048
#define D_ 512
#define H_ 8
#define NT 8192               // B*S tokens
#define DH 4096               // D*H
#define ZN 32                 // B*H attention instances
#define ATT_SCALE 0.04419417382415922f   // 512^-0.5

// ---------------- scratch (device globals; no runtime allocation) -------------
__device__ __half g_xn[(size_t)NT * D_];               // 8 MB
__device__ __half g_q[(size_t)ZN * S_ * D_];           // 64 MB [z][s][d] (pre-scaled)
__device__ __half g_k[(size_t)ZN * S_ * D_];           // 64 MB [z][s][d]
__device__ __half g_v[(size_t)ZN * S_ * D_];           // 64 MB [z][s][d]
__device__ __half g_vt[(size_t)ZN * S_ * D_];          // 64 MB [z][d][s]
__device__ __half g_p[(size_t)ZN * S_ * S_];           // 256 MB fp16 exp(logits)
__device__ float  g_partial[(size_t)ZN * S_ * 64];     // 16 MB per-row partial sums
__device__ float  g_rowsum[(size_t)ZN * S_];           // 256 KB 1/rowsum
__device__ __half g_attn[(size_t)NT * DH];             // 64 MB [token][h*512+d]
__device__ __half g_wtq[(size_t)DH * D_];              // 4 MB  W^T [4096][512]
__device__ __half g_wtk[(size_t)DH * D_];
__device__ __half g_wtv[(size_t)DH * D_];
__device__ __half g_wto[(size_t)D_ * DH];              // 4 MB  o_w^T [512][4096]

// ---------------- helpers -----------------------------------------------------
__device__ __forceinline__ uint32_t smem_u32(const void* p) {
    uint32_t a;
    asm("{ .reg .u64 t; cvta.to.shared.u64 t, %1; cvt.u32.u64 %0, t; }" : "=r"(a) : "l"(p));
    return a;
}
__device__ __forceinline__ void cp16(uint32_t dst, const void* src) {
    asm volatile("cp.async.cg.shared.global [%0], [%1], 16;" :: "r"(dst), "l"(src));
}
#define CP_COMMIT() asm volatile("cp.async.commit_group;")
#define CP_WAIT1()  asm volatile("cp.async.wait_group 1;")

__device__ __forceinline__ void ldsm_x4(uint32_t* r, uint32_t addr) {
    asm volatile("ldmatrix.sync.aligned.m8n8.x4.shared.b16 {%0,%1,%2,%3}, [%4];"
        : "=r"(r[0]), "=r"(r[1]), "=r"(r[2]), "=r"(r[3]) : "r"(addr));
}
__device__ __forceinline__ void mma_f16(float* c, const uint32_t* a, const uint32_t* b) {
    asm volatile(
        "mma.sync.aligned.m16n8k16.row.col.f32.f16.f16.f32 "
        "{%0,%1,%2,%3}, {%4,%5,%6,%7}, {%8,%9}, {%0,%1,%2,%3};"
        : "+f"(c[0]), "+f"(c[1]), "+f"(c[2]), "+f"(c[3])
        : "r"(a[0]), "r"(a[1]), "r"(a[2]), "r"(a[3]), "r"(b[0]), "r"(b[1]));
}

// ---------------- LayerNorm (fp32 in -> fp16 out) -----------------------------
__global__ void ln_kernel(const float* __restrict__ x,
                          const float* __restrict__ w,
                          const float* __restrict__ b) {
    int row = blockIdx.x;
    int t = threadIdx.x;                       // 128 threads, 4 floats each
    const float4* xr = (const float4*)(x + (size_t)row * D_);
    float4 v = xr[t];
    float s  = v.x + v.y + v.z + v.w;
    float q  = v.x * v.x + v.y * v.y + v.z * v.z + v.w * v.w;
#pragma unroll
    for (int o = 16; o > 0; o >>= 1) {
        s += __shfl_xor_sync(0xffffffffu, s, o);
        q += __shfl_xor_sync(0xffffffffu, q, o);
    }
    __shared__ float ss[4], sq[4];
    int wid = t >> 5;
    if ((t & 31) == 0) { ss[wid] = s; sq[wid] = q; }
    __syncthreads();
    s = ss[0] + ss[1] + ss[2] + ss[3];
    q = sq[0] + sq[1] + sq[2] + sq[3];
    float mu  = s * (1.0f / D_);
    float var = q * (1.0f / D_) - mu * mu;
    float r   = rsqrtf(var + 1e-5f);
    float4 wv = ((const float4*)w)[t];
    float4 bv = ((const float4*)b)[t];
    __half2 h0 = __floats2half2_rn((v.x - mu) * r * wv.x + bv.x,
                                   (v.y - mu) * r * wv.y + bv.y);
    __half2 h1 = __floats2half2_rn((v.z - mu) * r * wv.z + bv.z,
                                   (v.w - mu) * r * wv.w + bv.w);
    __half2* dst = (__half2*)(g_xn + (size_t)row * D_);
    dst[2 * t]     = h0;
    dst[2 * t + 1] = h1;
}

// ---------------- 32x32 tiled transpose ---------------------------------------
// sel 0..3: fp32 weights in -> half out. sel 4: half V -> half Vt per z.
__global__ void transpose_kernel(const float* __restrict__ in_f32, int sel, int R, int C) {
    __shared__ float tile[32][33];
    int z = blockIdx.z;
    __half* out;
    const __half* in_h = nullptr;
    if (sel == 0)      out = g_wtq;
    else if (sel == 1) out = g_wtk;
    else if (sel == 2) out = g_wtv;
    else if (sel == 3) out = g_wto;
    else { in_h = g_v + (size_t)z * S_ * D_; out = g_vt + (size_t)z * S_ * D_; }

    int x  = blockIdx.x * 32 + threadIdx.x;
    int y0 = blockIdx.y * 32;
#pragma unroll
    for (int j = 0; j < 32; j += 8) {
        float v;
        if (sel < 4) v = in_f32[(size_t)(y0 + threadIdx.y + j) * C + x];
        else         v = __half2float(in_h[(size_t)(y0 + threadIdx.y + j) * C + x]);
        tile[threadIdx.y + j][threadIdx.x] = v;
    }
    __syncthreads();
    int ox  = y0 + threadIdx.x;
    int oy0 = blockIdx.x * 32;
#pragma unroll
    for (int j = 0; j < 32; j += 8)
        out[(size_t)(oy0 + threadIdx.y + j) * R + ox] =
            __float2half_rn(tile[threadIdx.x][threadIdx.y + j]);
}

// ---------------- rowsum reduce: g_partial[row][64] -> 1/sum ------------------
__global__ void rowsum_kernel() {
    int row = blockIdx.x * 128 + threadIdx.x;            // 65536 rows
    const float4* p = (const float4*)(g_partial + (size_t)row * 64);
    float s = 0.f;
#pragma unroll
    for (int i = 0; i < 16; i++) {
        float4 v = p[i];
        s += (v.x + v.y) + (v.z + v.w);
    }
    g_rowsum[row] = 1.0f / s;
}

// ---------------- fp16 mma.sync GEMM, 3-stage cp.async pipeline ---------------
// Both operands K-major fp16. A [M,K], B [N,K]. fp32 accumulate.
// MODE 0: g_xn @ Wt(which)^T -> q(/scale)/k/v half (+bias)
// MODE 1: Qs @ K^T -> exp -> g_p fp16 + row partial sums (per z)
// MODE 2: E @ Vt^T * (1/rowsum) -> g_attn half (per z)
// MODE 3: g_attn @ Wto^T     -> out fp32 (+bias)
constexpr int STG = 3;
constexpr int OPBYTES = 128 * 40 * 2;            // one operand tile: 10240 B
constexpr int STGBYTES = 2 * OPBYTES;            // A+B per stage: 20480 B
constexpr int GEMM_SMEM = STG * STGBYTES;        // 61440 B

template <int MODE>
__global__ __launch_bounds__(256, 2)
void gemm_tc(const float* __restrict__ bias, float* __restrict__ Cout, int which) {
    constexpr int K   = (MODE == 0) ? 512 : (MODE == 1) ? 512 : (MODE == 2) ? 2048 : 4096;
    constexpr int lda = (MODE == 2) ? 2048 : (MODE == 3) ? 4096 : 512;
    constexpr int ldb = (MODE == 2) ? 2048 : (MODE == 3) ? 4096 : 512;
    constexpr int T   = K / 32;

    extern __shared__ __half sh[];
    uint32_t sbase = smem_u32(sh);

    int tid = threadIdx.x;
    int lane = tid & 31, wid = tid >> 5;
    int warp_m = wid & 1, warp_n = wid >> 1;   // 2 x 4 warps -> 64 x 32 per warp
    int z = blockIdx.z;
    int m0 = blockIdx.y * 128, n0 = blockIdx.x * 128;

    const __half* A;
    const __half* Bm;
    if (MODE == 0)      { A = g_xn;
                          Bm = (which == 0) ? g_wtq : (which == 1) ? g_wtk : g_wtv; }
    else if (MODE == 1) { A = g_q + (size_t)z * S_ * D_; Bm = g_k + (size_t)z * S_ * D_; }
    else if (MODE == 2) { A = g_p + ((size_t)z << 22);   Bm = g_vt + (size_t)z * S_ * D_; }
    else                { A = g_attn; Bm = g_wto; }
    A  += (size_t)m0 * lda;
    Bm += (size_t)n0 * ldb;

    float c[4][4][4];
#pragma unroll
    for (int i = 0; i < 4; i++)
#pragma unroll
        for (int j = 0; j < 4; j++)
#pragma unroll
            for (int e = 0; e < 4; e++) c[i][j][e] = 0.0f;

    // tile fill: 128 rows x 32 halves (64B) per operand = 512 x 16B; 2 per thread
    int lrow = tid >> 2, lseg = tid & 3;       // first half; second adds 64 rows
    auto tile_load = [&](int stg, int k0) {
        uint32_t abase = sbase + (uint32_t)stg * STGBYTES;
#pragma unroll
        for (int i = 0; i < 2; i++) {
            int row = lrow + i * 64;
            uint32_t off = (uint32_t)row * 80 + (uint32_t)lseg * 16;
            cp16(abase + off,           A  + (size_t)row * lda + k0 + lseg * 8);
            cp16(abase + OPBYTES + off, Bm + (size_t)row * ldb + k0 + lseg * 8);
        }
        CP_COMMIT();
    };

    // ldmatrix lane geometry (byte offsets within one operand tile)
    int rowA = warp_m * 64 + (lane & 7) + ((lane & 8) ? 8 : 0);
    int kA   = (lane & 16) ? 8 : 0;
    int rowB = warp_n * 32 + (lane & 7) + ((lane & 16) ? 8 : 0);
    int kB   = (lane & 8) ? 8 : 0;

    // prologue: prefetch STG-1 tiles
    tile_load(0, 0);
    tile_load(1, 32);

    for (int t = 0; t < T; t++) {
        int buf = t % STG;
        CP_WAIT1();                 // stage t landed (tail commits are empty groups)
        __syncthreads();            // all warps done with stage t-1's buffer
        {
            int tn = t + STG - 1;
            if (tn < T) tile_load(tn % STG, tn * 32);
            else        CP_COMMIT();      // empty group keeps the wait count aligned
        }

        uint32_t abase = sbase + (uint32_t)buf * STGBYTES;
        uint32_t bbase = abase + OPBYTES;
#pragma unroll
        for (int kf = 0; kf < 2; kf++) {
            uint32_t a[4][4], b[2][4];
#pragma unroll
            for (int im = 0; im < 4; im++)
                ldsm_x4(a[im], abase + (uint32_t)(rowA + im * 16) * 80
                                     + (uint32_t)(kA + kf * 16) * 2);
#pragma unroll
            for (int jp = 0; jp < 2; jp++)
                ldsm_x4(b[jp], bbase + (uint32_t)(rowB + jp * 16) * 80
                                     + (uint32_t)(kB + kf * 16) * 2);
#pragma unroll
            for (int im = 0; im < 4; im++)
#pragma unroll
                for (int jn = 0; jn < 4; jn++)
                    mma_f16(c[im][jn], a[im], &b[jn >> 1][(jn & 1) * 2]);
        }
    }
    __syncthreads();

    // ---- epilogue: thread owns cols (cc, cc+1) at rows r0 and r0+8 ----
    float rs[4][2];
    if (MODE == 1) {
#pragma unroll
        for (int i = 0; i < 4; i++) { rs[i][0] = 0.f; rs[i][1] = 0.f; }
    }
#pragma unroll
    for (int im = 0; im < 4; im++) {
#pragma unroll
        for (int jn = 0; jn < 4; jn++) {
            int r0 = m0 + warp_m * 64 + im * 16 + (lane >> 2);
            int cc = n0 + warp_n * 32 + jn * 8 + (lane & 3) * 2;
            float2 lo = make_float2(c[im][jn][0], c[im][jn][1]);
            float2 hi = make_float2(c[im][jn][2], c[im][jn][3]);

            if (MODE == 0) {
                float2 bv = *(const float2*)&bias[cc];
                lo.x += bv.x; lo.y += bv.y;
                hi.x += bv.x; hi.y += bv.y;
                if (which == 0) {   // pre-scale Q
                    lo.x *= ATT_SCALE; lo.y *= ATT_SCALE;
                    hi.x *= ATT_SCALE; hi.y *= ATT_SCALE;
                }
                __half* C = (which == 0) ? g_q : (which == 1) ? g_k : g_v;
                int h = cc >> 9, d = cc & 511;
                int b0 = r0 >> 11, s0 = r0 & 2047;
                *(__half2*)(C + ((size_t)(b0 * 8 + h) * S_ + s0) * D_ + d) =
                    __floats2half2_rn(lo.x, lo.y);
                int b1 = (r0 + 8) >> 11, s1 = (r0 + 8) & 2047;
                *(__half2*)(C + ((size_t)(b1 * 8 + h) * S_ + s1) * D_ + d) =
                    __floats2half2_rn(hi.x, hi.y);
            } else if (MODE == 1) {
                // unnormalized softmax numerator: exp(logit), fp16 store
                float e0 = __expf(lo.x), e1 = __expf(lo.y);
                float e2 = __expf(hi.x), e3 = __expf(hi.y);
                rs[im][0] += e0 + e1;
                rs[im][1] += e2 + e3;
                __half* base = g_p + ((size_t)z << 22) + cc;
                *(__half2*)(base + (size_t)r0 * S_) = __floats2half2_rn(e0, e1);
                *(__half2*)(base + (size_t)(r0 + 8) * S_) = __floats2half2_rn(e2, e3);
            } else if (MODE == 2) {
                float inv0 = g_rowsum[(size_t)z * S_ + r0];
                float inv1 = g_rowsum[(size_t)z * S_ + r0 + 8];
                lo.x *= inv0; lo.y *= inv0;
                hi.x *= inv1; hi.y *= inv1;
                int b = z >> 3, h = z & 7;
                __half* base = g_attn + (size_t)(b * S_) * DH + h * 512 + cc;
                *(__half2*)(base + (size_t)r0 * DH) = __floats2half2_rn(lo.x, lo.y);
                *(__half2*)(base + (size_t)(r0 + 8) * DH) = __floats2half2_rn(hi.x, hi.y);
            } else {
                float2 bv = *(const float2*)&bias[cc];
                lo.x += bv.x; lo.y += bv.y;
                hi.x += bv.x; hi.y += bv.y;
                *(float2*)(Cout + (size_t)r0 * D_ + cc) = lo;
                *(float2*)(Cout + (size_t)(r0 + 8) * D_ + cc) = hi;
            }
        }
    }

    if (MODE == 1) {
        // quad-reduce: lanes sharing a row differ only in (lane & 3)
#pragma unroll
        for (int im = 0; im < 4; im++) {
#pragma unroll
            for (int h2 = 0; h2 < 2; h2++) {
                float v = rs[im][h2];
                v += __shfl_xor_sync(0xffffffffu, v, 1);
                v += __shfl_xor_sync(0xffffffffu, v, 2);
                if ((lane & 3) == 0) {
                    int grow = m0 + warp_m * 64 + im * 16 + (lane >> 2) + h2 * 8;
                    g_partial[((size_t)z * S_ + grow) * 64 + blockIdx.x * 4 + warp_n] = v;
                }
            }
        }
    }
}

// ---------------- launch ------------------------------------------------------
extern "C" void kernel_launch(void* const* d_in, const int* in_sizes, int n_in,
                              void* d_out, int out_size) {
    const float* x    = (const float*)d_in[0];
    const float* ln_w = (const float*)d_in[1];
    const float* ln_b = (const float*)d_in[2];
    const float* q_w  = (const float*)d_in[3];
    const float* q_b  = (const float*)d_in[4];
    const float* k_w  = (const float*)d_in[5];
    const float* k_b  = (const float*)d_in[6];
    const float* v_w  = (const float*)d_in[7];
    const float* v_b  = (const float*)d_in[8];
    const float* o_w  = (const float*)d_in[9];
    const float* o_b  = (const float*)d_in[10];
    float* out = (float*)d_out;

    static bool attr_done = false;
    if (!attr_done) {
        cudaFuncSetAttribute(gemm_tc<0>, cudaFuncAttributeMaxDynamicSharedMemorySize, GEMM_SMEM);
        cudaFuncSetAttribute(gemm_tc<1>, cudaFuncAttributeMaxDynamicSharedMemorySize, GEMM_SMEM);
        cudaFuncSetAttribute(gemm_tc<2>, cudaFuncAttributeMaxDynamicSharedMemorySize, GEMM_SMEM);
        cudaFuncSetAttribute(gemm_tc<3>, cudaFuncAttributeMaxDynamicSharedMemorySize, GEMM_SMEM);
        attr_done = true;
    }

    dim3 tb(32, 8);
    ln_kernel<<<NT, 128>>>(x, ln_w, ln_b);
    transpose_kernel<<<dim3(128, 16, 1), tb>>>(q_w, 0, 512, 4096);
    transpose_kernel<<<dim3(128, 16, 1), tb>>>(k_w, 1, 512, 4096);
    transpose_kernel<<<dim3(128, 16, 1), tb>>>(v_w, 2, 512, 4096);
    transpose_kernel<<<dim3(16, 128, 1), tb>>>(o_w, 3, 4096, 512);

    dim3 gQKV(DH / 128, NT / 128, 1);                      // (32, 64)
    gemm_tc<0><<<gQKV, 256, GEMM_SMEM>>>(q_b, nullptr, 0);
    gemm_tc<0><<<gQKV, 256, GEMM_SMEM>>>(k_b, nullptr, 1);
    gemm_tc<0><<<gQKV, 256, GEMM_SMEM>>>(v_b, nullptr, 2);

    // V transpose per z: [2048,512] -> [512,2048]
    transpose_kernel<<<dim3(16, 64, ZN), tb>>>(nullptr, 4, 2048, 512);

    dim3 gS(S_ / 128, S_ / 128, ZN);                       // (16, 16, 32)
    gemm_tc<1><<<gS, 256, GEMM_SMEM>>>(nullptr, nullptr, 0);

    rowsum_kernel<<<ZN * S_ / 128, 128>>>();

    dim3 gPV(D_ / 128, S_ / 128, ZN);                      // (4, 16, 32)
    gemm_tc<2><<<gPV, 256, GEMM_SMEM>>>(nullptr, nullptr, 0);

    dim3 gO(D_ / 128, NT / 128, 1);                        // (4, 64)
    gemm_tc<3><<<gO, 256, GEMM_SMEM>>>(o_b, out, 0);
}